// round 1
// baseline (speedup 1.0000x reference)
#include <cuda_runtime.h>
#include <cuda_bf16.h>

// Problem shape (fixed by the dataset)
#define B_DIM 256
#define N_DIM 2048
#define K_DIM 2048
#define T_DIM 128

// LIF constants (match reference: alpha = exp(-0.1) rounded to f32)
#define ALPHA_F 0.9048374180359595731f
#define THRESH_F 1.0f

// Scratch for the input current I = x @ W  (2 MB, device global — no allocs allowed)
__device__ float g_I[B_DIM * N_DIM];

// ---------------------------------------------------------------------------
// Kernel 1: fp32 GEMM  I[b,n] = sum_k x[b,k] * W[k,n]
// 64x64 CTA tile, BK=16, 256 threads, 4x4 microtile per thread.
// With W = eye the result is exact in any accumulation order, so fmaf is safe.
// ---------------------------------------------------------------------------
#define BM 64
#define BN 64
#define BK 16
#define TM 4
#define TN 4

__global__ void __launch_bounds__(256, 2) gemm_kernel(
    const float* __restrict__ X,   // [B_DIM, K_DIM]
    const float* __restrict__ W)   // [K_DIM, N_DIM]
{
    // +4 pad keeps 16B alignment for float4 reads and breaks store bank patterns
    __shared__ float As[BK][BM + 4];   // transposed A tile: As[k][m]
    __shared__ float Bs[BK][BN];       // Bs[k][n]

    const int tid  = threadIdx.x;
    const int row0 = blockIdx.y * BM;  // m offset
    const int col0 = blockIdx.x * BN;  // n offset

    // A-tile load mapping: 64 rows x 16 k, one float4 (along k) per thread
    const int a_i = tid >> 2;          // 0..63  (m within tile)
    const int a_j = (tid & 3) * 4;     // 0..12  (k within tile)
    // B-tile load mapping: 16 k x 64 n, one float4 (along n) per thread
    const int b_i = tid >> 4;          // 0..15  (k within tile)
    const int b_j = (tid & 15) * 4;    // 0..60  (n within tile)

    // compute mapping
    const int ty = tid >> 4;           // 0..15 -> m group
    const int tx = tid & 15;           // 0..15 -> n group

    float acc[TM][TN];
#pragma unroll
    for (int i = 0; i < TM; i++)
#pragma unroll
        for (int j = 0; j < TN; j++) acc[i][j] = 0.0f;

    for (int k0 = 0; k0 < K_DIM; k0 += BK) {
        const float4 av = *reinterpret_cast<const float4*>(
            X + (size_t)(row0 + a_i) * K_DIM + (k0 + a_j));
        const float4 bv = *reinterpret_cast<const float4*>(
            W + (size_t)(k0 + b_i) * N_DIM + (col0 + b_j));

        As[a_j + 0][a_i] = av.x;
        As[a_j + 1][a_i] = av.y;
        As[a_j + 2][a_i] = av.z;
        As[a_j + 3][a_i] = av.w;
        *reinterpret_cast<float4*>(&Bs[b_i][b_j]) = bv;
        __syncthreads();

#pragma unroll
        for (int kk = 0; kk < BK; kk++) {
            const float4 a4 = *reinterpret_cast<const float4*>(&As[kk][ty * TM]);
            const float4 b4 = *reinterpret_cast<const float4*>(&Bs[kk][tx * TN]);
            const float a[TM] = {a4.x, a4.y, a4.z, a4.w};
            const float b[TN] = {b4.x, b4.y, b4.z, b4.w};
#pragma unroll
            for (int i = 0; i < TM; i++)
#pragma unroll
                for (int j = 0; j < TN; j++)
                    acc[i][j] = fmaf(a[i], b[j], acc[i][j]);
        }
        __syncthreads();
    }

    // Epilogue: write 4x4 microtile as float4 rows
#pragma unroll
    for (int i = 0; i < TM; i++) {
        float4 o = make_float4(acc[i][0], acc[i][1], acc[i][2], acc[i][3]);
        *reinterpret_cast<float4*>(
            g_I + (size_t)(row0 + ty * TM + i) * N_DIM + (col0 + tx * TN)) = o;
    }
}

// ---------------------------------------------------------------------------
// Kernel 2: LIF recurrence. Each thread owns 4 consecutive neurons (float4
// stores, fully coalesced per time step).
//   u      = rn(rn(ALPHA * V) + I)        <- explicit mul/add, NO fma
//                                            (XLA does not contract by default)
//   V_next = Z ? 0 : u                    <- (1 - Z) multiply, exact
//   Z_next = (V_next >= 1) ? 1 : 0
// ---------------------------------------------------------------------------
__global__ void __launch_bounds__(256) spike_kernel(float* __restrict__ out)
{
    const int g  = blockIdx.x * blockDim.x + threadIdx.x;   // 0 .. B*N/4
    const int n4 = g % (N_DIM / 4);
    const int b  = g / (N_DIM / 4);

    const float4 I4 = *reinterpret_cast<const float4*>(g_I + (size_t)b * N_DIM + n4 * 4);

    float v0 = 0.f, v1 = 0.f, v2 = 0.f, v3 = 0.f;
    bool  s0 = false, s1 = false, s2 = false, s3 = false;

    float* outp = out + (size_t)b * T_DIM * N_DIM + n4 * 4;

#pragma unroll 8
    for (int t = 0; t < T_DIM; t++) {
        float u0 = __fadd_rn(__fmul_rn(ALPHA_F, v0), I4.x);
        float u1 = __fadd_rn(__fmul_rn(ALPHA_F, v1), I4.y);
        float u2 = __fadd_rn(__fmul_rn(ALPHA_F, v2), I4.z);
        float u3 = __fadd_rn(__fmul_rn(ALPHA_F, v3), I4.w);
        v0 = s0 ? 0.0f : u0;
        v1 = s1 ? 0.0f : u1;
        v2 = s2 ? 0.0f : u2;
        v3 = s3 ? 0.0f : u3;
        s0 = (v0 >= THRESH_F);
        s1 = (v1 >= THRESH_F);
        s2 = (v2 >= THRESH_F);
        s3 = (v3 >= THRESH_F);
        float4 z = make_float4(s0 ? 1.0f : 0.0f, s1 ? 1.0f : 0.0f,
                               s2 ? 1.0f : 0.0f, s3 ? 1.0f : 0.0f);
        *reinterpret_cast<float4*>(outp) = z;
        outp += N_DIM;
    }
}

// ---------------------------------------------------------------------------
extern "C" void kernel_launch(void* const* d_in, const int* in_sizes, int n_in,
                              void* d_out, int out_size)
{
    const float* x = (const float*)d_in[0];   // [256, 2048]
    const float* W = (const float*)d_in[1];   // [2048, 2048]
    float* out = (float*)d_out;               // [256, 128, 2048]

    dim3 gemm_grid(N_DIM / BN, B_DIM / BM);   // (32, 4) = 128 CTAs
    gemm_kernel<<<gemm_grid, 256>>>(x, W);

    const int spike_threads = (B_DIM * N_DIM) / 4;  // 131072
    spike_kernel<<<spike_threads / 256, 256>>>(out);
}

// round 2
// speedup vs baseline: 1.6170x; 1.6170x over previous
#include <cuda_runtime.h>
#include <cuda_bf16.h>

// Problem shape (fixed by the dataset)
#define B_DIM 256
#define N_DIM 2048
#define K_DIM 2048
#define T_DIM 128

// LIF constants (alpha = exp(-0.1) rounded to f32)
#define ALPHA_F 0.9048374180359595731f
#define THRESH_F 1.0f

#define SPLITK 2
#define KS (K_DIM / SPLITK)   // 1024

// Partial sums for I = x @ W: [SPLITK][B][N]  (4 MB device scratch)
__device__ float g_I[SPLITK * B_DIM * N_DIM];

// Packed dual fp32 FMA (Blackwell f32x2) — bit-exact rn FMA per lane,
// but 2 FMAs per issue slot (ptxas never emits FFMA2 from C++).
#define FMA_F32X2(d, a, b, c) \
    asm("fma.rn.f32x2 %0, %1, %2, %3;" : "=l"(d) : "l"(a), "l"(b), "l"(c))
#define PACK_F32X2(out, lo, hi) \
    asm("mov.b64 %0, {%1, %2};" : "=l"(out) : "f"(lo), "f"(hi))

// ---------------------------------------------------------------------------
// Kernel 1: fp32 GEMM partials  I_part[z][b,n] = sum_{k in z-th K half} x[b,k]*W[k,n]
// 64x64 CTA tile, BK=16, 256 threads, 4x4 microtile (as 4x2 f32x2 pairs),
// double-buffered smem, grid (32, 4, 2) = 256 CTAs.
// ---------------------------------------------------------------------------
#define BM 64
#define BN 64
#define BK 16
#define TM 4
#define TN 4

__global__ void __launch_bounds__(256, 2) gemm_kernel(
    const float* __restrict__ X,   // [B_DIM, K_DIM]
    const float* __restrict__ W)   // [K_DIM, N_DIM]
{
    // +4 pad: row stride 68 floats = 272 B (16B multiple, so float4 LDS stays legal)
    __shared__ float As[2][BK][BM + 4];
    __shared__ float Bs[2][BK][BN + 4];

    const int tid  = threadIdx.x;
    const int col0 = blockIdx.x * BN;
    const int row0 = blockIdx.y * BM;
    const int kz   = blockIdx.z;

    // A-tile load: 64 m x 16 k, one float4 along k per thread
    const int a_i = tid >> 2;           // m in tile
    const int a_j = (tid & 3) * 4;      // k in tile
    // B-tile load: 16 k x 64 n, one float4 along n per thread
    const int b_i = tid >> 4;           // k in tile
    const int b_j = (tid & 15) * 4;     // n in tile

    const int ty = tid >> 4;            // m group (x4)
    const int tx = tid & 15;            // n group (x4)

    const float* Xp = X + (size_t)(row0 + a_i) * K_DIM + kz * KS + a_j;
    const float* Wp = W + (size_t)(kz * KS + b_i) * N_DIM + col0 + b_j;

    unsigned long long acc[TM][2];
#pragma unroll
    for (int i = 0; i < TM; i++) { acc[i][0] = 0ull; acc[i][1] = 0ull; }

    // prologue: tile 0 -> buffer 0
    float4 av = *reinterpret_cast<const float4*>(Xp);
    float4 bv = *reinterpret_cast<const float4*>(Wp);
    As[0][a_j + 0][a_i] = av.x;
    As[0][a_j + 1][a_i] = av.y;
    As[0][a_j + 2][a_i] = av.z;
    As[0][a_j + 3][a_i] = av.w;
    *reinterpret_cast<float4*>(&Bs[0][b_i][b_j]) = bv;
    __syncthreads();

    const int NT = KS / BK;   // 64 k-tiles
    int buf = 0;
    for (int kt = 0; kt < NT; kt++) {
        // prefetch next tile into registers (overlaps with compute below)
        if (kt + 1 < NT) {
            av = *reinterpret_cast<const float4*>(Xp + (kt + 1) * BK);
            bv = *reinterpret_cast<const float4*>(Wp + (size_t)(kt + 1) * BK * N_DIM);
        }

#pragma unroll
        for (int kk = 0; kk < BK; kk++) {
            const float4 a4 = *reinterpret_cast<const float4*>(&As[buf][kk][ty * TM]);
            const ulonglong2 b2 = *reinterpret_cast<const ulonglong2*>(&Bs[buf][kk][tx * TN]);
            unsigned long long ap;
            PACK_F32X2(ap, a4.x, a4.x);
            FMA_F32X2(acc[0][0], ap, b2.x, acc[0][0]);
            FMA_F32X2(acc[0][1], ap, b2.y, acc[0][1]);
            PACK_F32X2(ap, a4.y, a4.y);
            FMA_F32X2(acc[1][0], ap, b2.x, acc[1][0]);
            FMA_F32X2(acc[1][1], ap, b2.y, acc[1][1]);
            PACK_F32X2(ap, a4.z, a4.z);
            FMA_F32X2(acc[2][0], ap, b2.x, acc[2][0]);
            FMA_F32X2(acc[2][1], ap, b2.y, acc[2][1]);
            PACK_F32X2(ap, a4.w, a4.w);
            FMA_F32X2(acc[3][0], ap, b2.x, acc[3][0]);
            FMA_F32X2(acc[3][1], ap, b2.y, acc[3][1]);
        }

        // store prefetched tile into the other buffer (disjoint from compute buffer)
        if (kt + 1 < NT) {
            const int nb = buf ^ 1;
            As[nb][a_j + 0][a_i] = av.x;
            As[nb][a_j + 1][a_i] = av.y;
            As[nb][a_j + 2][a_i] = av.z;
            As[nb][a_j + 3][a_i] = av.w;
            *reinterpret_cast<float4*>(&Bs[nb][b_i][b_j]) = bv;
        }
        __syncthreads();
        buf ^= 1;
    }

    // Epilogue: 4 rows of 16B stores into this split's partial buffer
    float* outI = g_I + (size_t)kz * B_DIM * N_DIM;
#pragma unroll
    for (int i = 0; i < TM; i++) {
        ulonglong2 o;
        o.x = acc[i][0];
        o.y = acc[i][1];
        *reinterpret_cast<ulonglong2*>(
            outI + (size_t)(row0 + ty * TM + i) * N_DIM + (col0 + tx * TN)) = o;
    }
}

// ---------------------------------------------------------------------------
// Kernel 2: LIF recurrence. Each thread owns 4 consecutive neurons.
//   u = rn(rn(ALPHA*V) + I)   (explicit mul/add — XLA does not contract to FMA)
//   V' = Z ? 0 : u ;  Z' = (V' >= 1)
// Streaming 16B stores (write-only 256 MB, evict-first).
// ---------------------------------------------------------------------------
__global__ void __launch_bounds__(256) spike_kernel(float* __restrict__ out)
{
    const int g  = blockIdx.x * blockDim.x + threadIdx.x;   // 0 .. B*N/4
    const int n4 = g % (N_DIM / 4);
    const int b  = g / (N_DIM / 4);

    const float4 p0 = *reinterpret_cast<const float4*>(
        g_I + (size_t)b * N_DIM + n4 * 4);
    const float4 p1 = *reinterpret_cast<const float4*>(
        g_I + (size_t)(B_DIM + b) * N_DIM + n4 * 4);
    // exact: one partial is x, the other exactly 0 (and fp32 add matches ref order anyway)
    const float4 I4 = make_float4(__fadd_rn(p0.x, p1.x), __fadd_rn(p0.y, p1.y),
                                  __fadd_rn(p0.z, p1.z), __fadd_rn(p0.w, p1.w));

    float v0 = 0.f, v1 = 0.f, v2 = 0.f, v3 = 0.f;
    bool  s0 = false, s1 = false, s2 = false, s3 = false;

    float* outp = out + (size_t)b * T_DIM * N_DIM + n4 * 4;

#pragma unroll 8
    for (int t = 0; t < T_DIM; t++) {
        float u0 = __fadd_rn(__fmul_rn(ALPHA_F, v0), I4.x);
        float u1 = __fadd_rn(__fmul_rn(ALPHA_F, v1), I4.y);
        float u2 = __fadd_rn(__fmul_rn(ALPHA_F, v2), I4.z);
        float u3 = __fadd_rn(__fmul_rn(ALPHA_F, v3), I4.w);
        v0 = s0 ? 0.0f : u0;
        v1 = s1 ? 0.0f : u1;
        v2 = s2 ? 0.0f : u2;
        v3 = s3 ? 0.0f : u3;
        s0 = (v0 >= THRESH_F);
        s1 = (v1 >= THRESH_F);
        s2 = (v2 >= THRESH_F);
        s3 = (v3 >= THRESH_F);
        float4 z = make_float4(s0 ? 1.0f : 0.0f, s1 ? 1.0f : 0.0f,
                               s2 ? 1.0f : 0.0f, s3 ? 1.0f : 0.0f);
        __stcs(reinterpret_cast<float4*>(outp), z);
        outp += N_DIM;
    }
}

// ---------------------------------------------------------------------------
extern "C" void kernel_launch(void* const* d_in, const int* in_sizes, int n_in,
                              void* d_out, int out_size)
{
    const float* x = (const float*)d_in[0];   // [256, 2048]
    const float* W = (const float*)d_in[1];   // [2048, 2048]
    float* out = (float*)d_out;               // [256, 128, 2048]

    dim3 gemm_grid(N_DIM / BN, B_DIM / BM, SPLITK);   // (32, 4, 2) = 256 CTAs
    gemm_kernel<<<gemm_grid, 256>>>(x, W);

    const int spike_threads = (B_DIM * N_DIM) / 4;    // 131072
    spike_kernel<<<spike_threads / 256, 256>>>(out);
}